// round 8
// baseline (speedup 1.0000x reference)
#include <cuda_runtime.h>
#include <cstdint>

// 3x3 stride-1 pad-1 conv, 1 channel, weight = w * outer(kx,kx), kx=[den,1,den].
// x: (16,1,2048,2048) fp32 -> out same shape.
// Rolling 4-tile pipeline per CTA with double-buffered cp.async fills:
// tile t+1 always streams while tile t computes -> loads stay in flight
// continuously. Streaming stores (__stcs) keep the write stream out of L2 LRU.

#define TCOLS 128
#define TROWS 32
#define NTILE 4              // y-tiles per CTA (128 rows)
#define SROWS 34             // TROWS + 2
#define PITCH 136            // 4 + 128 + 4 floats
#define NCHUNK (SROWS * 34)  // 1156 float4 chunks per tile

__global__ __launch_bounds__(256)
void conv3x3_roll4(const float* __restrict__ x,
                   const float* __restrict__ w,
                   const float* __restrict__ den,
                   float* __restrict__ out,
                   int H, int W)
{
    __shared__ float tile[2][SROWS * PITCH];

    const int tid  = threadIdx.x;
    const int lane = tid & 31;
    const int wid  = tid >> 5;

    const int colbase = blockIdx.x * TCOLS;
    const int row00   = blockIdx.y * (TROWS * NTILE);   // first row of this CTA's strip
    const int b       = blockIdx.z;

    const size_t img = (size_t)H * W;
    const float* __restrict__ xb = x + (size_t)b * img;
    float*       __restrict__ ob = out + (size_t)b * img;

    // ---- R4-proven fill of one tile buffer (row0 = tile's first output row) ----
    auto fill = [&](int buf, int row0) {
        const uint32_t sbase = (uint32_t)__cvta_generic_to_shared(&tile[buf][0]);
        for (int c2 = tid; c2 < NCHUNK; c2 += 256) {
            const int r  = c2 / 34;
            const int cc = c2 - r * 34;
            const int gy = row0 - 1 + r;
            const int gx = colbase - 4 + 4 * cc;
            const bool valid = ((unsigned)gy < (unsigned)H) & ((unsigned)gx < (unsigned)W);
            const int off = valid ? (gy * W + gx) : 0;
            const int ss  = valid ? 16 : 0;
            const uint32_t dst = sbase + (uint32_t)(r * PITCH + 4 * cc) * 4u;
            asm volatile("cp.async.cg.shared.global [%0], [%1], 16, %2;"
                         :: "r"(dst), "l"(xb + off), "r"(ss));
        }
        asm volatile("cp.async.commit_group;");
    };

    fill(0, row00);   // prologue: tile 0

    // effective 3x3 weights (overlaps with first fill)
    const float d = den[0];
    const float kv[3] = {d, 1.0f, d};
    float k[9];
    #pragma unroll
    for (int i = 0; i < 3; i++)
        #pragma unroll
        for (int j = 0; j < 3; j++)
            k[i * 3 + j] = __ldg(&w[i * 3 + j]) * kv[i] * kv[j];

    const int base_f = 4 * lane;
    const int lr0 = 4 * wid;   // warp's first input smem row; outputs [4w, 4w+4)

    auto compute = [&](int buf, int row0) {
        const float* tb = &tile[buf][0];
        auto ldrow = [&](int r, float* s) {
            const float* p = tb + r * PITCH + base_f;
            const float4 v = *reinterpret_cast<const float4*>(p + 4);
            s[0] = p[3]; s[1] = v.x; s[2] = v.y; s[3] = v.z; s[4] = v.w; s[5] = p[8];
        };

        float s0[6], s1[6], s2[6];
        ldrow(lr0,     s0);
        ldrow(lr0 + 1, s1);

        float* ro = ob + (size_t)(row0 + lr0) * W + colbase + base_f;

        #pragma unroll
        for (int oo = 0; oo < 4; oo++) {
            ldrow(lr0 + 2 + oo, s2);

            float a0 = 0.f, a1 = 0.f, a2 = 0.f, a3 = 0.f;
            #pragma unroll
            for (int i = 0; i < 3; i++) {
                const float* s = (i == 0) ? s0 : (i == 1) ? s1 : s2;
                const float w0 = k[3 * i], w1 = k[3 * i + 1], w2 = k[3 * i + 2];
                a0 = fmaf(w0, s[0], fmaf(w1, s[1], fmaf(w2, s[2], a0)));
                a1 = fmaf(w0, s[1], fmaf(w1, s[2], fmaf(w2, s[3], a1)));
                a2 = fmaf(w0, s[2], fmaf(w1, s[3], fmaf(w2, s[4], a2)));
                a3 = fmaf(w0, s[3], fmaf(w1, s[4], fmaf(w2, s[5], a3)));
            }
            __stcs(reinterpret_cast<float4*>(ro), make_float4(a0, a1, a2, a3));
            ro += W;

            #pragma unroll
            for (int i = 0; i < 6; i++) { s0[i] = s1[i]; s1[i] = s2[i]; }
        }
    };

    // ---- rolling pipeline over NTILE tiles ----
    #pragma unroll
    for (int t = 0; t < NTILE; t++) {
        if (t + 1 < NTILE) {
            fill((t + 1) & 1, row00 + (t + 1) * TROWS);
            asm volatile("cp.async.wait_group 1;");   // tile t ready, t+1 in flight
        } else {
            asm volatile("cp.async.wait_group 0;");   // last tile
        }
        __syncthreads();                // tile t visible to all warps
        compute(t & 1, row00 + t * TROWS);
        __syncthreads();                // all warps done with buf (t&1) before refill at t+2
    }
}

extern "C" void kernel_launch(void* const* d_in, const int* in_sizes, int n_in,
                              void* d_out, int out_size)
{
    const float* x   = (const float*)d_in[0];   // (16,1,2048,2048) fp32
    const float* w   = (const float*)d_in[1];   // (1,1,3,3) fp32
    const float* den = (const float*)d_in[2];   // (1,) fp32
    float* out = (float*)d_out;

    const int B = 16, H = 2048, W = 2048;
    (void)in_sizes; (void)n_in; (void)out_size;

    dim3 grid(W / TCOLS, H / (TROWS * NTILE), B);   // 16 x 16 x 16 = 4096 CTAs
    dim3 block(256);
    conv3x3_roll4<<<grid, block>>>(x, w, den, out, H, W);
}

// round 9
// speedup vs baseline: 1.0378x; 1.0378x over previous
#include <cuda_runtime.h>
#include <cstdint>

// 3x3 stride-1 pad-1 conv, 1 channel, weight = w * outer(kx,kx), kx=[den,1,den].
// x: (16,1,2048,2048) fp32 -> out same shape.
// R4 champion structure (one-shot cp.async tile fill, 93% occ, DRAM 75%)
// + streaming (evict-first) output stores to reduce L2 r/w interference.

#define TCOLS 128            // output cols per CTA
#define TROWS 32             // output rows per CTA
#define PITCH 136            // smem row pitch in floats (4 + 128 + 4)
#define SROWS 34             // smem rows (TROWS + 2)
#define NCHUNK (SROWS * 34)  // float4 chunks per tile (34 per row)

__global__ __launch_bounds__(256)
void conv3x3_final(const float* __restrict__ x,
                   const float* __restrict__ w,
                   const float* __restrict__ den,
                   float* __restrict__ out,
                   int H, int W)
{
    __shared__ float tile[SROWS * PITCH];

    const int tid  = threadIdx.x;
    const int lane = tid & 31;
    const int wid  = tid >> 5;

    const int colbase = blockIdx.x * TCOLS;
    const int row0    = blockIdx.y * TROWS;
    const int b       = blockIdx.z;

    const size_t img = (size_t)H * W;
    const float* __restrict__ xb = x + (size_t)b * img;
    float*       __restrict__ ob = out + (size_t)b * img;

    // ---------------- one-shot async tile load: 34 rows x 34 float4 chunks ----------------
    // smem float f of row r  <->  gmem (row0-1+r, colbase-4+f)
    {
        const uint32_t sbase = (uint32_t)__cvta_generic_to_shared(tile);
        #pragma unroll
        for (int c2 = tid; c2 < NCHUNK; c2 += 256) {
            const int r  = c2 / 34;
            const int cc = c2 - r * 34;
            const int gy = row0 - 1 + r;
            const int gx = colbase - 4 + 4 * cc;
            const bool valid = ((unsigned)gy < (unsigned)H) & ((unsigned)gx < (unsigned)W);
            const int off = valid ? (gy * W + gx) : 0;      // clamp ptr when zfilled
            const int srcsize = valid ? 16 : 0;
            const uint32_t daddr = sbase + (uint32_t)(r * PITCH + 4 * cc) * 4u;
            asm volatile("cp.async.cg.shared.global [%0], [%1], 16, %2;"
                         :: "r"(daddr), "l"(xb + off), "r"(srcsize));
        }
        asm volatile("cp.async.commit_group;");
    }

    // effective 3x3 weights (overlaps with loads in flight)
    const float d = den[0];
    const float kv[3] = {d, 1.0f, d};
    float k[9];
    #pragma unroll
    for (int i = 0; i < 3; i++)
        #pragma unroll
        for (int j = 0; j < 3; j++)
            k[i * 3 + j] = __ldg(&w[i * 3 + j]) * kv[i] * kv[j];

    asm volatile("cp.async.wait_group 0;");
    __syncthreads();

    // ---------------- compute: warp w -> output rows [4w, 4w+4) ----------------
    const int base_f = 4 * lane;
    auto ldrow = [&](int r, float* s) {
        const float* p = &tile[r * PITCH + base_f];
        const float4 v = *reinterpret_cast<const float4*>(p + 4);
        s[0] = p[3]; s[1] = v.x; s[2] = v.y; s[3] = v.z; s[4] = v.w; s[5] = p[8];
    };

    float s0[6], s1[6], s2[6];
    const int lr0 = 4 * wid;        // local smem row of first needed input row
    ldrow(lr0,     s0);
    ldrow(lr0 + 1, s1);

    float* ro = ob + (size_t)(row0 + 4 * wid) * W + colbase + base_f;

    #pragma unroll
    for (int oo = 0; oo < 4; oo++) {
        ldrow(lr0 + 2 + oo, s2);

        float a0 = 0.f, a1 = 0.f, a2 = 0.f, a3 = 0.f;
        #pragma unroll
        for (int i = 0; i < 3; i++) {
            const float* s = (i == 0) ? s0 : (i == 1) ? s1 : s2;
            const float w0 = k[3 * i], w1 = k[3 * i + 1], w2 = k[3 * i + 2];
            a0 = fmaf(w0, s[0], fmaf(w1, s[1], fmaf(w2, s[2], a0)));
            a1 = fmaf(w0, s[1], fmaf(w1, s[2], fmaf(w2, s[3], a1)));
            a2 = fmaf(w0, s[2], fmaf(w1, s[3], fmaf(w2, s[4], a2)));
            a3 = fmaf(w0, s[3], fmaf(w1, s[4], fmaf(w2, s[5], a3)));
        }
        __stcs(reinterpret_cast<float4*>(ro), make_float4(a0, a1, a2, a3));
        ro += W;

        #pragma unroll
        for (int i = 0; i < 6; i++) { s0[i] = s1[i]; s1[i] = s2[i]; }
    }
}

extern "C" void kernel_launch(void* const* d_in, const int* in_sizes, int n_in,
                              void* d_out, int out_size)
{
    const float* x   = (const float*)d_in[0];   // (16,1,2048,2048) fp32
    const float* w   = (const float*)d_in[1];   // (1,1,3,3) fp32
    const float* den = (const float*)d_in[2];   // (1,) fp32
    float* out = (float*)d_out;

    const int B = 16, H = 2048, W = 2048;
    (void)in_sizes; (void)n_in; (void)out_size;

    dim3 grid(W / TCOLS, H / TROWS, B);   // 16 x 64 x 16 = 16384 CTAs
    dim3 block(256);
    conv3x3_final<<<grid, block>>>(x, w, den, out, H, W);
}